// round 1
// baseline (speedup 1.0000x reference)
#include <cuda_runtime.h>
#include <math.h>

#define Nn 1024
#define Cc 8192
#define Dd 16
#define ODim 128
#define EPSF 1e-15f
#define CLIPMAXF 10000.0f

// ---------------- scratch (device globals, no allocation) ----------------
__device__ float  g_cL[Nn * Dd];
__device__ float  g_cH[Nn * Dd];
__device__ float  g_inner[Nn];
__device__ float  g_colR[Nn];     // sum over i of realDist[i][j]
__device__ float  g_colA[Nn];     // sum over i of omegaDist[i][j]
__device__ double g_sumsqR;
__device__ double g_sumsqA;
__device__ double g_overlap;
__device__ double g_exceed;
__device__ double g_shape;
__device__ double g_positive;

// ---------------- zero init ----------------
__global__ void k_zero() {
    int t = blockIdx.x * blockDim.x + threadIdx.x;
    if (t < Nn) { g_colR[t] = 0.f; g_colA[t] = 0.f; }
    if (t == 0) {
        g_sumsqR = 0.0; g_sumsqA = 0.0; g_overlap = 0.0;
        g_exceed = 0.0; g_shape = 0.0; g_positive = 0.0;
    }
}

// ---------------- prep: gather cL/cH, per-node losses, omega norms ----------------
__global__ void k_prep(const int* __restrict__ idI, const int* __restrict__ par,
                       const float* __restrict__ omega, const float* __restrict__ child,
                       const float* __restrict__ resv, const float* __restrict__ leaves) {
    int n = blockIdx.x * blockDim.x + threadIdx.x;
    if (n >= Nn) return;
    int id = idI[n];
    int p  = par[n];
    float leaf = leaves[id];
    const float HPI = (float)(3.14159265358979323846 * 0.5);
    const float CAP = (float)(3.14159265358979323846 * 0.49999);

    float exceed = 0.f, shape = 0.f, pos = 0.f;
#pragma unroll
    for (int d = 0; d < Dd; d++) {
        float cl = child[id * 2 * Dd + d];
        float ch = child[id * 2 * Dd + Dd + d];
        g_cL[n * Dd + d] = cl;
        g_cH[n * Dd + d] = ch;
        float diff = ch - cl;
        float rl = resv[p * 2 * Dd + d];
        float rh = resv[p * 2 * Dd + Dd + d];
        // lossExceed
        exceed += fmaxf((rl + 1.0f) - cl, 0.f) + fmaxf(ch - (rh + 1.0f), 0.f);
        // lossShapeLike
        float numer = fmaxf(diff / (rh - rl), EPSF);
        float sdiv  = fminf(numer / leaf, CAP);
        shape += fminf(fabsf(tanf((sdiv - 1.0f) * HPI)), CLIPMAXF);
        // lossPositive
        pos += fmaxf(expf(-diff), EPSF);
    }
    // omega squared norm
    const float4* o4 = (const float4*)(omega + (size_t)n * ODim);
    float s = 0.f;
#pragma unroll
    for (int q = 0; q < ODim / 4; q++) {
        float4 v = o4[q];
        s += v.x * v.x + v.y * v.y + v.z * v.z + v.w * v.w;
    }
    g_inner[n] = s;

    // warp-reduce scalars -> double atomics
    double e = exceed, sh = shape, po = pos;
#pragma unroll
    for (int off = 16; off > 0; off >>= 1) {
        e  += __shfl_xor_sync(0xffffffffu, e,  off);
        sh += __shfl_xor_sync(0xffffffffu, sh, off);
        po += __shfl_xor_sync(0xffffffffu, po, off);
    }
    if ((threadIdx.x & 31) == 0) {
        atomicAdd(&g_exceed,   e);
        atomicAdd(&g_shape,    sh);
        atomicAdd(&g_positive, po);
    }
}

// ---------------- N x N pass: realDist colsums/sumsq + overlap ----------------
// grid: 128 blocks x 256 threads; block handles 8 rows i, thread handles 4 cols j.
__global__ void k_real(const int* __restrict__ idI, const float* __restrict__ layerDist) {
    extern __shared__ float sh[];
    float* sCL = sh;                 // Nn*Dd
    float* sCH = sh + Nn * Dd;       // Nn*Dd
    int*   sIdx = (int*)(sh + 2 * Nn * Dd);  // Nn
    int tid = threadIdx.x;

    for (int t = tid; t < Nn * Dd; t += 256) { sCL[t] = g_cL[t]; sCH[t] = g_cH[t]; }
    for (int t = tid; t < Nn; t += 256) sIdx[t] = idI[t];
    __syncthreads();

    float csum[4] = {0.f, 0.f, 0.f, 0.f};
    double sumsq = 0.0, ovacc = 0.0;
    int i0 = blockIdx.x * 8;

    for (int ii = 0; ii < 8; ii++) {
        int i = i0 + ii;
        float cLi[Dd], cHi[Dd], invd[Dd];
        const float4* a4 = (const float4*)(sCL + i * Dd);
        const float4* b4 = (const float4*)(sCH + i * Dd);
#pragma unroll
        for (int q = 0; q < 4; q++) {
            float4 va = a4[q], vb = b4[q];
            cLi[4*q+0] = va.x; cLi[4*q+1] = va.y; cLi[4*q+2] = va.z; cLi[4*q+3] = va.w;
            cHi[4*q+0] = vb.x; cHi[4*q+1] = vb.y; cHi[4*q+2] = vb.z; cHi[4*q+3] = vb.w;
        }
#pragma unroll
        for (int d = 0; d < Dd; d++) invd[d] = 1.0f / fmaxf(cHi[d] - cLi[d], EPSF);

        size_t rowOff = (size_t)sIdx[i] * Cc;
        float ssf = 0.f, ovf = 0.f;
#pragma unroll
        for (int jj = 0; jj < 4; jj++) {
            int j = tid + jj * 256;
            float acc = __ldg(layerDist + rowOff + sIdx[j]);
            const float4* jl4 = (const float4*)(sCL + j * Dd);
            const float4* jh4 = (const float4*)(sCH + j * Dd);
            float cd = 0.f, o = 0.f;
#pragma unroll
            for (int q = 0; q < 4; q++) {
                float4 lj = jl4[q];
                float4 hj = jh4[q];
                cd += fabsf(cLi[4*q+0] - lj.x) + fabsf(cLi[4*q+1] - lj.y)
                    + fabsf(cLi[4*q+2] - lj.z) + fabsf(cLi[4*q+3] - lj.w);
                o += fmaxf(fminf(cHi[4*q+0], hj.x) - fmaxf(cLi[4*q+0], lj.x), 0.f) * invd[4*q+0];
                o += fmaxf(fminf(cHi[4*q+1], hj.y) - fmaxf(cLi[4*q+1], lj.y), 0.f) * invd[4*q+1];
                o += fmaxf(fminf(cHi[4*q+2], hj.z) - fmaxf(cLi[4*q+2], lj.z), 0.f) * invd[4*q+2];
                o += fmaxf(fminf(cHi[4*q+3], hj.w) - fmaxf(cLi[4*q+3], lj.w), 0.f) * invd[4*q+3];
            }
            float r = acc + cd;
            csum[jj] += r;
            ssf += r * r;
            if (i != j) ovf += o;
        }
        sumsq += (double)ssf;
        ovacc += (double)ovf;
    }

#pragma unroll
    for (int jj = 0; jj < 4; jj++) atomicAdd(&g_colR[tid + jj * 256], csum[jj]);

#pragma unroll
    for (int off = 16; off > 0; off >>= 1) {
        sumsq += __shfl_xor_sync(0xffffffffu, sumsq, off);
        ovacc += __shfl_xor_sync(0xffffffffu, ovacc, off);
    }
    if ((tid & 31) == 0) {
        atomicAdd(&g_sumsqR, sumsq);
        atomicAdd(&g_overlap, ovacc);
    }
}

// ---------------- omegaDist: O*O^T tiled GEMM + reductions ----------------
// 64x64 tile, 256 threads, 4x4 micro-tile, K staged in 2 chunks of 64.
__global__ void k_omega(const float* __restrict__ omega) {
    __shared__ float sA[64 * 64];   // k-major: sA[k*64 + i]
    __shared__ float sB[64 * 64];   // k-major: sB[k*64 + j]
    __shared__ float scol[64];
    int tid = threadIdx.x;
    int bi = blockIdx.y * 64;
    int bj = blockIdx.x * 64;
    if (tid < 64) scol[tid] = 0.f;

    float c[4][4];
#pragma unroll
    for (int m = 0; m < 4; m++)
#pragma unroll
        for (int n = 0; n < 4; n++) c[m][n] = 0.f;

    int tx = tid & 15, ty = tid >> 4;

    for (int kc = 0; kc < ODim; kc += 64) {
        __syncthreads();
        for (int t = tid; t < 64 * 16; t += 256) {
            int r = t & 63, qq = t >> 6;
            float4 va = ((const float4*)omega)[(size_t)(bi + r) * (ODim / 4) + (kc >> 2) + qq];
            float4 vb = ((const float4*)omega)[(size_t)(bj + r) * (ODim / 4) + (kc >> 2) + qq];
            int k = qq * 4;
            sA[(k + 0) * 64 + r] = va.x; sA[(k + 1) * 64 + r] = va.y;
            sA[(k + 2) * 64 + r] = va.z; sA[(k + 3) * 64 + r] = va.w;
            sB[(k + 0) * 64 + r] = vb.x; sB[(k + 1) * 64 + r] = vb.y;
            sB[(k + 2) * 64 + r] = vb.z; sB[(k + 3) * 64 + r] = vb.w;
        }
        __syncthreads();
#pragma unroll 8
        for (int k = 0; k < 64; k++) {
            float4 av = *(const float4*)&sA[k * 64 + ty * 4];
            float4 bv = *(const float4*)&sB[k * 64 + tx * 4];
            c[0][0] += av.x * bv.x; c[0][1] += av.x * bv.y; c[0][2] += av.x * bv.z; c[0][3] += av.x * bv.w;
            c[1][0] += av.y * bv.x; c[1][1] += av.y * bv.y; c[1][2] += av.y * bv.z; c[1][3] += av.y * bv.w;
            c[2][0] += av.z * bv.x; c[2][1] += av.z * bv.y; c[2][2] += av.z * bv.z; c[2][3] += av.z * bv.w;
            c[3][0] += av.w * bv.x; c[3][1] += av.w * bv.y; c[3][2] += av.w * bv.z; c[3][3] += av.w * bv.w;
        }
    }

    float innI[4], innJ[4];
#pragma unroll
    for (int m = 0; m < 4; m++) innI[m] = g_inner[bi + ty * 4 + m];
#pragma unroll
    for (int n = 0; n < 4; n++) innJ[n] = g_inner[bj + tx * 4 + n];

    float colloc[4] = {0.f, 0.f, 0.f, 0.f};
    float ssf = 0.f;
#pragma unroll
    for (int m = 0; m < 4; m++)
#pragma unroll
        for (int n = 0; n < 4; n++) {
            float a = fmaxf(innI[m] + innJ[n] - 2.0f * c[m][n], EPSF);
            ssf += a * a;
            colloc[n] += a;
        }
#pragma unroll
    for (int n = 0; n < 4; n++) atomicAdd(&scol[tx * 4 + n], colloc[n]);

    double ss = (double)ssf;
#pragma unroll
    for (int off = 16; off > 0; off >>= 1)
        ss += __shfl_xor_sync(0xffffffffu, ss, off);
    if ((tid & 31) == 0) atomicAdd(&g_sumsqA, ss);

    __syncthreads();
    if (tid < 64) atomicAdd(&g_colA[bj + tid], scol[tid]);
}

// ---------------- finalize ----------------
__global__ void k_final(float* __restrict__ out) {
    __shared__ double red1[32], red2[32];
    int t = threadIdx.x;
    double nR = fmax(sqrt(g_sumsqR), 1e-15);
    double nA = fmax(sqrt(g_sumsqA), 1e-15);
    double b  = (double)g_colR[t] / nR;
    double s1 = b * (double)g_colA[t];
    double s2 = b * b;
#pragma unroll
    for (int off = 16; off > 0; off >>= 1) {
        s1 += __shfl_xor_sync(0xffffffffu, s1, off);
        s2 += __shfl_xor_sync(0xffffffffu, s2, off);
    }
    if ((t & 31) == 0) { red1[t >> 5] = s1; red2[t >> 5] = s2; }
    __syncthreads();
    if (t < 32) {
        double a = red1[t], c = red2[t];
#pragma unroll
        for (int off = 16; off > 0; off >>= 1) {
            a += __shfl_xor_sync(0xffffffffu, a, off);
            c += __shfl_xor_sync(0xffffffffu, c, off);
        }
        if (t == 0) {
            double val = g_sumsqA / (nA * nA) - 2.0 * a / nA + (double)Nn * c;
            double lossDist = sqrt(fmax(val, 0.0));
            out[0] = (float)(lossDist + g_shape + g_exceed + g_overlap + g_positive);
        }
    }
}

// ---------------- launch ----------------
extern "C" void kernel_launch(void* const* d_in, const int* in_sizes, int n_in,
                              void* d_out, int out_size) {
    const int*   idI    = (const int*)d_in[0];
    const int*   par    = (const int*)d_in[1];
    const float* omega  = (const float*)d_in[2];
    const float* child  = (const float*)d_in[3];
    const float* resv   = (const float*)d_in[4];
    const float* leaves = (const float*)d_in[5];
    const float* layerD = (const float*)d_in[6];
    (void)in_sizes; (void)n_in; (void)out_size;

    const int smemR = (2 * Nn * Dd + Nn) * 4;  // 135168 B
    cudaFuncSetAttribute(k_real, cudaFuncAttributeMaxDynamicSharedMemorySize, smemR);

    k_zero<<<4, 256>>>();
    k_prep<<<4, 256>>>(idI, par, omega, child, resv, leaves);
    k_real<<<128, 256, smemR>>>(idI, layerD);
    dim3 gO(16, 16);
    k_omega<<<gO, 256>>>(omega);
    k_final<<<1, Nn>>>((float*)d_out);
}

// round 2
// speedup vs baseline: 1.2961x; 1.2961x over previous
#include <cuda_runtime.h>
#include <math.h>

#define Nn 1024
#define Cc 8192
#define Dd 16
#define ODim 128
#define EPSF 1e-15f
#define CLIPMAXF 10000.0f
#define NB 16                    // 1024/64 tiles per side
#define NTRI (NB*(NB+1)/2)       // 136 triangular tiles

// ---------------- scratch (device globals, no allocation) ----------------
__device__ float  g_cL[Nn * Dd];
__device__ float  g_cH[Nn * Dd];
__device__ float  g_inner[Nn];
__device__ float  g_colR[Nn];     // sum over i of realDist[i][j]
__device__ float  g_colA[Nn];     // sum over i of omegaDist[i][j]
__device__ double g_sumsqR;
__device__ double g_sumsqA;
__device__ double g_overlap;
__device__ double g_exceed;
__device__ double g_shape;
__device__ double g_positive;

// ---------------- prep (+ zero): gather cL/cH, per-node losses, omega norms ----
__global__ void k_prep(const int* __restrict__ idI, const int* __restrict__ par,
                       const float* __restrict__ omega, const float* __restrict__ child,
                       const float* __restrict__ resv, const float* __restrict__ leaves) {
    int n = blockIdx.x * blockDim.x + threadIdx.x;
    if (n >= Nn) return;
    // fused zeroing of accumulators
    g_colR[n] = 0.f;
    g_colA[n] = 0.f;
    if (n == 0) {
        g_sumsqR = 0.0; g_sumsqA = 0.0; g_overlap = 0.0;
        g_exceed = 0.0; g_shape = 0.0; g_positive = 0.0;
    }

    int id = idI[n];
    int p  = par[n];
    float leaf = leaves[id];
    const float HPI = (float)(3.14159265358979323846 * 0.5);
    const float CAP = (float)(3.14159265358979323846 * 0.49999);

    float exceed = 0.f, shape = 0.f, pos = 0.f;
#pragma unroll
    for (int d = 0; d < Dd; d++) {
        float cl = child[id * 2 * Dd + d];
        float ch = child[id * 2 * Dd + Dd + d];
        g_cL[n * Dd + d] = cl;
        g_cH[n * Dd + d] = ch;
        float diff = ch - cl;
        float rl = resv[p * 2 * Dd + d];
        float rh = resv[p * 2 * Dd + Dd + d];
        exceed += fmaxf((rl + 1.0f) - cl, 0.f) + fmaxf(ch - (rh + 1.0f), 0.f);
        float numer = fmaxf(diff / (rh - rl), EPSF);
        float sdiv  = fminf(numer / leaf, CAP);
        shape += fminf(fabsf(tanf((sdiv - 1.0f) * HPI)), CLIPMAXF);
        pos += fmaxf(expf(-diff), EPSF);
    }
    const float4* o4 = (const float4*)(omega + (size_t)n * ODim);
    float s = 0.f;
#pragma unroll
    for (int q = 0; q < ODim / 4; q++) {
        float4 v = o4[q];
        s += v.x * v.x + v.y * v.y + v.z * v.z + v.w * v.w;
    }
    g_inner[n] = s;

    double e = exceed, sh = shape, po = pos;
#pragma unroll
    for (int off = 16; off > 0; off >>= 1) {
        e  += __shfl_xor_sync(0xffffffffu, e,  off);
        sh += __shfl_xor_sync(0xffffffffu, sh, off);
        po += __shfl_xor_sync(0xffffffffu, po, off);
    }
    if ((threadIdx.x & 31) == 0) {
        atomicAdd(&g_exceed,   e);
        atomicAdd(&g_shape,    sh);
        atomicAdd(&g_positive, po);
    }
}

// ---------------- N x N pass: realDist colsums/sumsq + overlap ----------------
// grid 256 blocks x 512 threads. Block b: i-chunk = (b>>1)*8 .. +8, j-half = (b&1).
// Thread owns one j (cL/cH in registers); i-data broadcast from tiny smem.
__global__ void __launch_bounds__(512, 2)
k_real(const int* __restrict__ idI, const float* __restrict__ layerDist) {
    __shared__ __align__(16) float sI[8][48];   // [ii][0:16)=cL, [16:32)=cH, [32:48)=inv
    int tid = threadIdx.x;
    int i0 = (blockIdx.x >> 1) * 8;
    int jglob = (blockIdx.x & 1) * 512 + tid;

    if (tid < 128) {
        int ii = tid >> 4, d = tid & 15;
        float cl = g_cL[(i0 + ii) * Dd + d];
        float ch = g_cH[(i0 + ii) * Dd + d];
        sI[ii][d]      = cl;
        sI[ii][16 + d] = ch;
        sI[ii][32 + d] = 1.0f / fmaxf(ch - cl, EPSF);
    }

    int idxj = __ldg(idI + jglob);
    float4 lj[4], hj[4];
    const float4* pl = (const float4*)(g_cL + (size_t)jglob * Dd);
    const float4* ph = (const float4*)(g_cH + (size_t)jglob * Dd);
#pragma unroll
    for (int q = 0; q < 4; q++) { lj[q] = pl[q]; hj[q] = ph[q]; }
    __syncthreads();

    // prefetch the 8 layerDist gathers (MLP=8)
    float acc[8];
#pragma unroll
    for (int ii = 0; ii < 8; ii++) {
        int idxi = __ldg(idI + i0 + ii);
        acc[ii] = __ldg(layerDist + (size_t)idxi * Cc + idxj);
    }

    float colsum = 0.f, ssqf = 0.f, ovf = 0.f;
#pragma unroll
    for (int ii = 0; ii < 8; ii++) {
        const float4* iL = (const float4*)&sI[ii][0];
        const float4* iH = (const float4*)&sI[ii][16];
        const float4* iV = (const float4*)&sI[ii][32];
        float cd = 0.f, o = 0.f;
#pragma unroll
        for (int q = 0; q < 4; q++) {
            float4 a = iL[q], b = iH[q], v = iV[q];
            float4 l = lj[q], h = hj[q];
            cd += fabsf(a.x - l.x) + fabsf(a.y - l.y)
                + fabsf(a.z - l.z) + fabsf(a.w - l.w);
            o += fmaxf(fminf(b.x, h.x) - fmaxf(a.x, l.x), 0.f) * v.x;
            o += fmaxf(fminf(b.y, h.y) - fmaxf(a.y, l.y), 0.f) * v.y;
            o += fmaxf(fminf(b.z, h.z) - fmaxf(a.z, l.z), 0.f) * v.z;
            o += fmaxf(fminf(b.w, h.w) - fmaxf(a.w, l.w), 0.f) * v.w;
        }
        float r = acc[ii] + cd;
        colsum += r;
        ssqf += r * r;
        if (i0 + ii != jglob) ovf += o;
    }

    atomicAdd(&g_colR[jglob], colsum);

    double ssq = (double)ssqf, ovd = (double)ovf;
#pragma unroll
    for (int off = 16; off > 0; off >>= 1) {
        ssq += __shfl_xor_sync(0xffffffffu, ssq, off);
        ovd += __shfl_xor_sync(0xffffffffu, ovd, off);
    }
    if ((tid & 31) == 0) {
        atomicAdd(&g_sumsqR, ssq);
        atomicAdd(&g_overlap, ovd);
    }
}

// ---------------- omegaDist: symmetric O*O^T, 136 triangular 64x64 tiles ------
// 256 threads, 4x4 microtile, conflict-free lane mapping (4 rows x 8 cols/warp).
__global__ void __launch_bounds__(256)
k_omega(const float* __restrict__ omega) {
    __shared__ float sA[32][64];   // k-major A slice
    __shared__ float sB[32][64];   // k-major B slice
    __shared__ float scol[64], srow[64];
    int tid = threadIdx.x;

    // decode triangular block index -> (bi, bj), bi <= bj
    int b = blockIdx.x, bi = 0;
    while (b >= NB - bi) { b -= NB - bi; bi++; }
    int bj = bi + b;
    bool diag = (bi == bj);

    if (tid < 64) { scol[tid] = 0.f; srow[tid] = 0.f; }

    float c[4][4];
#pragma unroll
    for (int m = 0; m < 4; m++)
#pragma unroll
        for (int n = 0; n < 4; n++) c[m][n] = 0.f;

    int w = tid >> 5, lane = tid & 31;
    int ri = lane >> 3;          // 0..3
    int cj = lane & 7;           // 0..7  -> 8 distinct float4 cols = all 32 banks
    int iloc = (w & 3) * 16 + ri * 4;
    int jloc = (w >> 2) * 32 + cj * 4;

    for (int kc = 0; kc < ODim; kc += 32) {
        __syncthreads();
#pragma unroll
        for (int s = 0; s < 2; s++) {
            int f = tid + s * 256;         // 0..511
            int r = f & 63, q = f >> 6;    // q in 0..7
            float4 va = ((const float4*)omega)[(size_t)(bi * 64 + r) * (ODim / 4) + (kc >> 2) + q];
            float4 vb = ((const float4*)omega)[(size_t)(bj * 64 + r) * (ODim / 4) + (kc >> 2) + q];
            sA[q * 4 + 0][r] = va.x; sA[q * 4 + 1][r] = va.y;
            sA[q * 4 + 2][r] = va.z; sA[q * 4 + 3][r] = va.w;
            sB[q * 4 + 0][r] = vb.x; sB[q * 4 + 1][r] = vb.y;
            sB[q * 4 + 2][r] = vb.z; sB[q * 4 + 3][r] = vb.w;
        }
        __syncthreads();
#pragma unroll
        for (int k = 0; k < 32; k++) {
            float4 av = *(const float4*)&sA[k][iloc];
            float4 bv = *(const float4*)&sB[k][jloc];
            c[0][0] += av.x * bv.x; c[0][1] += av.x * bv.y; c[0][2] += av.x * bv.z; c[0][3] += av.x * bv.w;
            c[1][0] += av.y * bv.x; c[1][1] += av.y * bv.y; c[1][2] += av.y * bv.z; c[1][3] += av.y * bv.w;
            c[2][0] += av.z * bv.x; c[2][1] += av.z * bv.y; c[2][2] += av.z * bv.z; c[2][3] += av.z * bv.w;
            c[3][0] += av.w * bv.x; c[3][1] += av.w * bv.y; c[3][2] += av.w * bv.z; c[3][3] += av.w * bv.w;
        }
    }

    float innI[4], innJ[4];
#pragma unroll
    for (int m = 0; m < 4; m++) innI[m] = g_inner[bi * 64 + iloc + m];
#pragma unroll
    for (int n = 0; n < 4; n++) innJ[n] = g_inner[bj * 64 + jloc + n];

    float colloc[4] = {0.f, 0.f, 0.f, 0.f};
    float rowloc[4] = {0.f, 0.f, 0.f, 0.f};
    float ssf = 0.f;
#pragma unroll
    for (int m = 0; m < 4; m++)
#pragma unroll
        for (int n = 0; n < 4; n++) {
            float a = fmaxf(innI[m] + innJ[n] - 2.0f * c[m][n], EPSF);
            ssf += a * a;
            colloc[n] += a;
            rowloc[m] += a;
        }
    if (!diag) ssf *= 2.0f;   // symmetric partner tile

#pragma unroll
    for (int n = 0; n < 4; n++) atomicAdd(&scol[jloc + n], colloc[n]);
    if (!diag) {
#pragma unroll
        for (int m = 0; m < 4; m++) atomicAdd(&srow[iloc + m], rowloc[m]);
    }

    double ss = (double)ssf;
#pragma unroll
    for (int off = 16; off > 0; off >>= 1)
        ss += __shfl_xor_sync(0xffffffffu, ss, off);
    if ((tid & 31) == 0) atomicAdd(&g_sumsqA, ss);

    __syncthreads();
    if (tid < 64) {
        atomicAdd(&g_colA[bj * 64 + tid], scol[tid]);
        if (!diag) atomicAdd(&g_colA[bi * 64 + tid], srow[tid]);
    }
}

// ---------------- finalize ----------------
__global__ void k_final(float* __restrict__ out) {
    __shared__ double red1[32], red2[32];
    int t = threadIdx.x;
    double nR = fmax(sqrt(g_sumsqR), 1e-15);
    double nA = fmax(sqrt(g_sumsqA), 1e-15);
    double b  = (double)g_colR[t] / nR;
    double s1 = b * (double)g_colA[t];
    double s2 = b * b;
#pragma unroll
    for (int off = 16; off > 0; off >>= 1) {
        s1 += __shfl_xor_sync(0xffffffffu, s1, off);
        s2 += __shfl_xor_sync(0xffffffffu, s2, off);
    }
    if ((t & 31) == 0) { red1[t >> 5] = s1; red2[t >> 5] = s2; }
    __syncthreads();
    if (t < 32) {
        double a = red1[t], c = red2[t];
#pragma unroll
        for (int off = 16; off > 0; off >>= 1) {
            a += __shfl_xor_sync(0xffffffffu, a, off);
            c += __shfl_xor_sync(0xffffffffu, c, off);
        }
        if (t == 0) {
            double val = g_sumsqA / (nA * nA) - 2.0 * a / nA + (double)Nn * c;
            double lossDist = sqrt(fmax(val, 0.0));
            out[0] = (float)(lossDist + g_shape + g_exceed + g_overlap + g_positive);
        }
    }
}

// ---------------- launch ----------------
extern "C" void kernel_launch(void* const* d_in, const int* in_sizes, int n_in,
                              void* d_out, int out_size) {
    const int*   idI    = (const int*)d_in[0];
    const int*   par    = (const int*)d_in[1];
    const float* omega  = (const float*)d_in[2];
    const float* child  = (const float*)d_in[3];
    const float* resv   = (const float*)d_in[4];
    const float* leaves = (const float*)d_in[5];
    const float* layerD = (const float*)d_in[6];
    (void)in_sizes; (void)n_in; (void)out_size;

    k_prep<<<4, 256>>>(idI, par, omega, child, resv, leaves);
    k_real<<<256, 512>>>(idI, layerD);
    k_omega<<<NTRI, 256>>>(omega);
    k_final<<<1, Nn>>>((float*)d_out);
}

// round 3
// speedup vs baseline: 1.5349x; 1.1842x over previous
#include <cuda_runtime.h>
#include <math.h>

#define Nn 1024
#define Cc 8192
#define Dd 16
#define ODim 128
#define EPSF 1e-15f
#define CLIPMAXF 10000.0f
#define NB 16                    // 1024/64 tiles per side
#define NTRI (NB*(NB+1)/2)       // 136 triangular tiles

// ---------- state (device globals; zero at load, re-zeroed by finalize) ----------
__device__ float    g_inner[Nn];
__device__ float    g_colR[Nn];
__device__ float    g_colA[Nn];
__device__ double   g_sumsqR;
__device__ double   g_sumsqA;
__device__ double   g_overlap;
__device__ double   g_exceed;
__device__ double   g_shape;
__device__ double   g_positive;
__device__ unsigned g_done;

// ================= K1: realDist pass + fused per-node prep ==================
// grid 256 x 512. block b: i-chunk=(b>>1)*8, j-half=(b&1). Blocks 0,1 also do
// per-node losses (exceed/shape/positive) and omega norms, reusing their
// register-resident cL/cH.
__global__ void __launch_bounds__(512, 2)
k_main(const int* __restrict__ idI, const int* __restrict__ par,
       const float* __restrict__ omega, const float* __restrict__ child,
       const float* __restrict__ resv, const float* __restrict__ leaves,
       const float* __restrict__ layerDist) {
    __shared__ __align__(16) float sI[8][48];   // [ii][0:16)=cL,[16:32)=cH,[32:48)=inv
    int tid = threadIdx.x;
    int b = blockIdx.x;
    int i0 = (b >> 1) * 8;
    int jglob = (b & 1) * 512 + tid;

    if (tid < 128) {
        int ii = tid >> 4, d = tid & 15;
        int idxi = __ldg(idI + i0 + ii);
        float cl = __ldg(child + (size_t)idxi * 32 + d);
        float ch = __ldg(child + (size_t)idxi * 32 + 16 + d);
        sI[ii][d]      = cl;
        sI[ii][16 + d] = ch;
        sI[ii][32 + d] = 1.0f / fmaxf(ch - cl, EPSF);
    }

    int idxj = __ldg(idI + jglob);
    float4 lj[4], hj[4];
    const float4* pl = (const float4*)(child + (size_t)idxj * 32);
    const float4* ph = (const float4*)(child + (size_t)idxj * 32 + 16);
#pragma unroll
    for (int q = 0; q < 4; q++) { lj[q] = pl[q]; hj[q] = ph[q]; }

    // prefetch 8 layerDist gathers (MLP=8)
    float acc[8];
#pragma unroll
    for (int ii = 0; ii < 8; ii++) {
        int idxi = __ldg(idI + i0 + ii);
        acc[ii] = __ldg(layerDist + (size_t)idxi * Cc + idxj);
    }
    __syncthreads();

    float colsum = 0.f, ssqf = 0.f, ovf = 0.f;
#pragma unroll
    for (int ii = 0; ii < 8; ii++) {
        const float4* iL = (const float4*)&sI[ii][0];
        const float4* iH = (const float4*)&sI[ii][16];
        const float4* iV = (const float4*)&sI[ii][32];
        float cd = 0.f, o = 0.f;
#pragma unroll
        for (int q = 0; q < 4; q++) {
            float4 a = iL[q], bb = iH[q], v = iV[q];
            float4 l = lj[q], h = hj[q];
            cd += fabsf(a.x - l.x) + fabsf(a.y - l.y)
                + fabsf(a.z - l.z) + fabsf(a.w - l.w);
            o += fmaxf(fminf(bb.x, h.x) - fmaxf(a.x, l.x), 0.f) * v.x;
            o += fmaxf(fminf(bb.y, h.y) - fmaxf(a.y, l.y), 0.f) * v.y;
            o += fmaxf(fminf(bb.z, h.z) - fmaxf(a.z, l.z), 0.f) * v.z;
            o += fmaxf(fminf(bb.w, h.w) - fmaxf(a.w, l.w), 0.f) * v.w;
        }
        float r = acc[ii] + cd;
        colsum += r;
        ssqf += r * r;
        if (i0 + ii != jglob) ovf += o;
    }

    atomicAdd(&g_colR[jglob], colsum);

    double ssq = (double)ssqf, ovd = (double)ovf;
#pragma unroll
    for (int off = 16; off > 0; off >>= 1) {
        ssq += __shfl_xor_sync(0xffffffffu, ssq, off);
        ovd += __shfl_xor_sync(0xffffffffu, ovd, off);
    }
    if ((tid & 31) == 0) {
        atomicAdd(&g_sumsqR, ssq);
        atomicAdd(&g_overlap, ovd);
    }

    // -------- fused prep: blocks 0,1 cover all nodes (jglob = node id) --------
    if (b < 2) {
        int n = jglob;
        int p = __ldg(par + n);
        float leaf = __ldg(leaves + idxj);
        const float HPI = (float)(3.14159265358979323846 * 0.5);
        const float CAP = (float)(3.14159265358979323846 * 0.49999);
        const float4* prl = (const float4*)(resv + (size_t)p * 32);
        const float4* prh = (const float4*)(resv + (size_t)p * 32 + 16);

        float exceed = 0.f, shape = 0.f, pos = 0.f;
#pragma unroll
        for (int q = 0; q < 4; q++) {
            float4 cl = lj[q], ch = hj[q];
            float4 rl = prl[q], rh = prh[q];
            float c[4] = {cl.x, cl.y, cl.z, cl.w};
            float e[4] = {ch.x, ch.y, ch.z, ch.w};
            float a[4] = {rl.x, rl.y, rl.z, rl.w};
            float z[4] = {rh.x, rh.y, rh.z, rh.w};
#pragma unroll
            for (int u = 0; u < 4; u++) {
                float diff = e[u] - c[u];
                exceed += fmaxf((a[u] + 1.0f) - c[u], 0.f) + fmaxf(e[u] - (z[u] + 1.0f), 0.f);
                float numer = fmaxf(diff / (z[u] - a[u]), EPSF);
                float sdiv  = fminf(numer / leaf, CAP);
                shape += fminf(fabsf(tanf((sdiv - 1.0f) * HPI)), CLIPMAXF);
                pos += fmaxf(expf(-diff), EPSF);
            }
        }
        const float4* o4 = (const float4*)(omega + (size_t)n * ODim);
        float s = 0.f;
#pragma unroll
        for (int q = 0; q < ODim / 4; q++) {
            float4 v = o4[q];
            s += v.x * v.x + v.y * v.y + v.z * v.z + v.w * v.w;
        }
        g_inner[n] = s;

        double e = exceed, sh = shape, po = pos;
#pragma unroll
        for (int off = 16; off > 0; off >>= 1) {
            e  += __shfl_xor_sync(0xffffffffu, e,  off);
            sh += __shfl_xor_sync(0xffffffffu, sh, off);
            po += __shfl_xor_sync(0xffffffffu, po, off);
        }
        if ((tid & 31) == 0) {
            atomicAdd(&g_exceed,   e);
            atomicAdd(&g_shape,    sh);
            atomicAdd(&g_positive, po);
        }
    }
}

// ========== K2: symmetric O*O^T (136 triangular tiles) + fused finalize ==========
__global__ void __launch_bounds__(256)
k_omega(const float* __restrict__ omega, float* __restrict__ out) {
    __shared__ float sA[32][64];
    __shared__ float sB[32][64];
    __shared__ float scol[64], srow[64];
    int tid = threadIdx.x;

    int b = blockIdx.x, bi = 0;
    while (b >= NB - bi) { b -= NB - bi; bi++; }
    int bj = bi + b;
    bool diag = (bi == bj);

    if (tid < 64) { scol[tid] = 0.f; srow[tid] = 0.f; }

    float c[4][4];
#pragma unroll
    for (int m = 0; m < 4; m++)
#pragma unroll
        for (int n = 0; n < 4; n++) c[m][n] = 0.f;

    int w = tid >> 5, lane = tid & 31;
    int ri = lane >> 3;
    int cj = lane & 7;
    int iloc = (w & 3) * 16 + ri * 4;
    int jloc = (w >> 2) * 32 + cj * 4;

    for (int kc = 0; kc < ODim; kc += 32) {
        __syncthreads();
#pragma unroll
        for (int s = 0; s < 2; s++) {
            int f = tid + s * 256;
            int r = f & 63, q = f >> 6;
            float4 va = ((const float4*)omega)[(size_t)(bi * 64 + r) * (ODim / 4) + (kc >> 2) + q];
            float4 vb = ((const float4*)omega)[(size_t)(bj * 64 + r) * (ODim / 4) + (kc >> 2) + q];
            sA[q * 4 + 0][r] = va.x; sA[q * 4 + 1][r] = va.y;
            sA[q * 4 + 2][r] = va.z; sA[q * 4 + 3][r] = va.w;
            sB[q * 4 + 0][r] = vb.x; sB[q * 4 + 1][r] = vb.y;
            sB[q * 4 + 2][r] = vb.z; sB[q * 4 + 3][r] = vb.w;
        }
        __syncthreads();
#pragma unroll
        for (int k = 0; k < 32; k++) {
            float4 av = *(const float4*)&sA[k][iloc];
            float4 bv = *(const float4*)&sB[k][jloc];
            c[0][0] += av.x * bv.x; c[0][1] += av.x * bv.y; c[0][2] += av.x * bv.z; c[0][3] += av.x * bv.w;
            c[1][0] += av.y * bv.x; c[1][1] += av.y * bv.y; c[1][2] += av.y * bv.z; c[1][3] += av.y * bv.w;
            c[2][0] += av.z * bv.x; c[2][1] += av.z * bv.y; c[2][2] += av.z * bv.z; c[2][3] += av.z * bv.w;
            c[3][0] += av.w * bv.x; c[3][1] += av.w * bv.y; c[3][2] += av.w * bv.z; c[3][3] += av.w * bv.w;
        }
    }

    float innI[4], innJ[4];
#pragma unroll
    for (int m = 0; m < 4; m++) innI[m] = g_inner[bi * 64 + iloc + m];
#pragma unroll
    for (int n = 0; n < 4; n++) innJ[n] = g_inner[bj * 64 + jloc + n];

    float colloc[4] = {0.f, 0.f, 0.f, 0.f};
    float rowloc[4] = {0.f, 0.f, 0.f, 0.f};
    float ssf = 0.f;
#pragma unroll
    for (int m = 0; m < 4; m++)
#pragma unroll
        for (int n = 0; n < 4; n++) {
            float a = fmaxf(innI[m] + innJ[n] - 2.0f * c[m][n], EPSF);
            ssf += a * a;
            colloc[n] += a;
            rowloc[m] += a;
        }
    if (!diag) ssf *= 2.0f;

#pragma unroll
    for (int n = 0; n < 4; n++) atomicAdd(&scol[jloc + n], colloc[n]);
    if (!diag) {
#pragma unroll
        for (int m = 0; m < 4; m++) atomicAdd(&srow[iloc + m], rowloc[m]);
    }

    double ss = (double)ssf;
#pragma unroll
    for (int off = 16; off > 0; off >>= 1)
        ss += __shfl_xor_sync(0xffffffffu, ss, off);
    if ((tid & 31) == 0) atomicAdd(&g_sumsqA, ss);

    __syncthreads();
    if (tid < 64) {
        atomicAdd(&g_colA[bj * 64 + tid], scol[tid]);
        if (!diag) atomicAdd(&g_colA[bi * 64 + tid], srow[tid]);
    }

    // ---------------- last-block finalize + state re-zero ----------------
    __threadfence();
    __shared__ bool isLast;
    if (tid == 0) isLast = (atomicAdd(&g_done, 1u) == NTRI - 1);
    __syncthreads();
    if (!isLast) return;
    __threadfence();

    double s1 = 0.0, s2 = 0.0;
#pragma unroll
    for (int q = 0; q < 4; q++) {
        int j = tid + q * 256;
        double r = (double)__ldcg(&g_colR[j]);
        double a = (double)__ldcg(&g_colA[j]);
        s1 += r * a;
        s2 += r * r;
        g_colR[j] = 0.f;
        g_colA[j] = 0.f;
    }
    __shared__ double r1[8], r2[8];
#pragma unroll
    for (int off = 16; off > 0; off >>= 1) {
        s1 += __shfl_xor_sync(0xffffffffu, s1, off);
        s2 += __shfl_xor_sync(0xffffffffu, s2, off);
    }
    if (lane == 0) { r1[w] = s1; r2[w] = s2; }
    __syncthreads();
    if (tid == 0) {
        double a = 0.0, cc2 = 0.0;
#pragma unroll
        for (int q = 0; q < 8; q++) { a += r1[q]; cc2 += r2[q]; }
        double sumsqR = __ldcg(&g_sumsqR);
        double sumsqA = __ldcg(&g_sumsqA);
        double nR = fmax(sqrt(sumsqR), 1e-15);
        double nA = fmax(sqrt(sumsqA), 1e-15);
        double val = sumsqA / (nA * nA) - 2.0 * (a / nR) / nA + (double)Nn * (cc2 / (nR * nR));
        double lossDist = sqrt(fmax(val, 0.0));
        out[0] = (float)(lossDist + __ldcg(&g_shape) + __ldcg(&g_exceed)
                         + __ldcg(&g_overlap) + __ldcg(&g_positive));
        // restore zeroed state for the next invocation
        g_sumsqR = 0.0; g_sumsqA = 0.0; g_overlap = 0.0;
        g_exceed = 0.0; g_shape = 0.0; g_positive = 0.0;
        g_done = 0u;
    }
}

// ---------------- launch ----------------
extern "C" void kernel_launch(void* const* d_in, const int* in_sizes, int n_in,
                              void* d_out, int out_size) {
    const int*   idI    = (const int*)d_in[0];
    const int*   par    = (const int*)d_in[1];
    const float* omega  = (const float*)d_in[2];
    const float* child  = (const float*)d_in[3];
    const float* resv   = (const float*)d_in[4];
    const float* leaves = (const float*)d_in[5];
    const float* layerD = (const float*)d_in[6];
    (void)in_sizes; (void)n_in; (void)out_size;

    k_main<<<256, 512>>>(idI, par, omega, child, resv, leaves, layerD);
    k_omega<<<NTRI, 256>>>(omega, (float*)d_out);
}

// round 4
// speedup vs baseline: 2.0560x; 1.3394x over previous
#include <cuda_runtime.h>
#include <math.h>

#define Nn 1024
#define Cc 8192
#define Dd 16
#define ODim 128
#define EPSF 1e-15f
#define CLIPMAXF 10000.0f
#define NB 16                      // 1024/64 tiles per side
#define NTRI (NB*(NB+1)/2)         // 136 triangular omega tiles
#define NREAL 256                  // real-dist blocks
#define NTOT (NTRI + NREAL)        // 392

// ---------- state (device globals; zero at load, re-zeroed by finalize) ----------
__device__ float    g_colR[Nn];
__device__ float    g_colA[Nn];
__device__ double   g_sumsqR;
__device__ double   g_sumsqA;
__device__ double   g_overlap;
__device__ double   g_exceed;
__device__ double   g_shape;
__device__ double   g_positive;
__device__ unsigned g_done;

// ================= single fused kernel ==================
// blocks [0, NTRI): symmetric O*O^T 64x64 triangular tiles (self-contained inner norms)
// blocks [NTRI, NTOT): realDist pass (8 i-rows x 512 j each); blocks NTRI, NTRI+1 also
// run per-node prep losses. Last finished block finalizes + re-zeros state.
__global__ void __launch_bounds__(256, 4)
k_all(const int* __restrict__ idI, const int* __restrict__ par,
      const float* __restrict__ omega, const float* __restrict__ child,
      const float* __restrict__ resv, const float* __restrict__ leaves,
      const float* __restrict__ layerDist, float* __restrict__ out) {
    __shared__ float sA[32][64];
    __shared__ float sB[32][64];
    __shared__ float sInnA[64], sInnB[64];
    __shared__ float scol[64], srow[64];
    __shared__ __align__(16) float sI[8][48];
    __shared__ bool isLast;

    int tid = threadIdx.x;
    int w = tid >> 5, lane = tid & 31;
    int b = blockIdx.x;

    if (b < NTRI) {
        // ================= omega tile =================
        int t = b, bi = 0;
        while (t >= NB - bi) { t -= NB - bi; bi++; }
        int bj = bi + t;
        bool diag = (bi == bj);

        if (tid < 64) { scol[tid] = 0.f; srow[tid] = 0.f; }

        float c[4][4];
#pragma unroll
        for (int m = 0; m < 4; m++)
#pragma unroll
            for (int n = 0; n < 4; n++) c[m][n] = 0.f;

        int ri = lane >> 3;
        int cj = lane & 7;
        int iloc = (w & 3) * 16 + ri * 4;
        int jloc = (w >> 2) * 32 + cj * 4;

        for (int kc = 0; kc < ODim; kc += 32) {
            __syncthreads();
#pragma unroll
            for (int s = 0; s < 2; s++) {
                int f = tid + s * 256;
                int r = f & 63, q = f >> 6;
                float4 va = ((const float4*)omega)[(size_t)(bi * 64 + r) * (ODim / 4) + (kc >> 2) + q];
                float4 vb = ((const float4*)omega)[(size_t)(bj * 64 + r) * (ODim / 4) + (kc >> 2) + q];
                sA[q * 4 + 0][r] = va.x; sA[q * 4 + 1][r] = va.y;
                sA[q * 4 + 2][r] = va.z; sA[q * 4 + 3][r] = va.w;
                sB[q * 4 + 0][r] = vb.x; sB[q * 4 + 1][r] = vb.y;
                sB[q * 4 + 2][r] = vb.z; sB[q * 4 + 3][r] = vb.w;
            }
            __syncthreads();
#pragma unroll
            for (int k = 0; k < 32; k++) {
                float4 av = *(const float4*)&sA[k][iloc];
                float4 bv = *(const float4*)&sB[k][jloc];
                c[0][0] += av.x * bv.x; c[0][1] += av.x * bv.y; c[0][2] += av.x * bv.z; c[0][3] += av.x * bv.w;
                c[1][0] += av.y * bv.x; c[1][1] += av.y * bv.y; c[1][2] += av.y * bv.z; c[1][3] += av.y * bv.w;
                c[2][0] += av.z * bv.x; c[2][1] += av.z * bv.y; c[2][2] += av.z * bv.z; c[2][3] += av.z * bv.w;
                c[3][0] += av.w * bv.x; c[3][1] += av.w * bv.y; c[3][2] += av.w * bv.z; c[3][3] += av.w * bv.w;
            }
        }

        // self-computed inner norms for this tile's rows/cols (L2-hot)
        if (tid < 128) {
            int r = tid & 63;
            int row = ((tid < 64) ? bi : bj) * 64 + r;
            const float4* p = (const float4*)(omega + (size_t)row * ODim);
            float s = 0.f;
#pragma unroll
            for (int q = 0; q < ODim / 4; q++) {
                float4 v = p[q];
                s += v.x * v.x + v.y * v.y + v.z * v.z + v.w * v.w;
            }
            if (tid < 64) sInnA[r] = s; else sInnB[r] = s;
        }
        __syncthreads();

        float innI[4], innJ[4];
#pragma unroll
        for (int m = 0; m < 4; m++) innI[m] = sInnA[iloc + m];
#pragma unroll
        for (int n = 0; n < 4; n++) innJ[n] = sInnB[jloc + n];

        float colloc[4] = {0.f, 0.f, 0.f, 0.f};
        float rowloc[4] = {0.f, 0.f, 0.f, 0.f};
        float ssf = 0.f;
#pragma unroll
        for (int m = 0; m < 4; m++)
#pragma unroll
            for (int n = 0; n < 4; n++) {
                float a = fmaxf(innI[m] + innJ[n] - 2.0f * c[m][n], EPSF);
                ssf += a * a;
                colloc[n] += a;
                rowloc[m] += a;
            }
        if (!diag) ssf *= 2.0f;

#pragma unroll
        for (int n = 0; n < 4; n++) atomicAdd(&scol[jloc + n], colloc[n]);
        if (!diag) {
#pragma unroll
            for (int m = 0; m < 4; m++) atomicAdd(&srow[iloc + m], rowloc[m]);
        }

        double ss = (double)ssf;
#pragma unroll
        for (int off = 16; off > 0; off >>= 1)
            ss += __shfl_xor_sync(0xffffffffu, ss, off);
        if (lane == 0) atomicAdd(&g_sumsqA, ss);

        __syncthreads();
        if (tid < 64) {
            atomicAdd(&g_colA[bj * 64 + tid], scol[tid]);
            if (!diag) atomicAdd(&g_colA[bi * 64 + tid], srow[tid]);
        }
    } else {
        // ================= realDist block =================
        int rb = b - NTRI;
        int i0 = (rb >> 1) * 8;

        if (tid < 128) {
            int ii = tid >> 4, d = tid & 15;
            int idxi = __ldg(idI + i0 + ii);
            float cl = __ldg(child + (size_t)idxi * 32 + d);
            float ch = __ldg(child + (size_t)idxi * 32 + 16 + d);
            sI[ii][d]      = cl;
            sI[ii][16 + d] = ch;
            sI[ii][32 + d] = 1.0f / fmaxf(ch - cl, EPSF);
        }
        int idxi8[8];
#pragma unroll
        for (int ii = 0; ii < 8; ii++) idxi8[ii] = __ldg(idI + i0 + ii);
        __syncthreads();

        double ssq = 0.0, ovd = 0.0;
        double eAcc = 0.0, shAcc = 0.0, poAcc = 0.0;
        bool doPrep = (rb < 2);

#pragma unroll
        for (int q = 0; q < 2; q++) {
            int jglob = (rb & 1) * 512 + q * 256 + tid;
            int idxj = __ldg(idI + jglob);
            float4 lj[4], hj[4];
            const float4* pl = (const float4*)(child + (size_t)idxj * 32);
            const float4* ph = (const float4*)(child + (size_t)idxj * 32 + 16);
#pragma unroll
            for (int u = 0; u < 4; u++) { lj[u] = pl[u]; hj[u] = ph[u]; }

            float acc[8];
#pragma unroll
            for (int ii = 0; ii < 8; ii++)
                acc[ii] = __ldg(layerDist + (size_t)idxi8[ii] * Cc + idxj);

            float colsum = 0.f, ssqf = 0.f, ovf = 0.f;
#pragma unroll
            for (int ii = 0; ii < 8; ii++) {
                const float4* iL = (const float4*)&sI[ii][0];
                const float4* iH = (const float4*)&sI[ii][16];
                const float4* iV = (const float4*)&sI[ii][32];
                float cd = 0.f, o = 0.f;
#pragma unroll
                for (int u = 0; u < 4; u++) {
                    float4 a = iL[u], bb = iH[u], v = iV[u];
                    float4 l = lj[u], h = hj[u];
                    cd += fabsf(a.x - l.x) + fabsf(a.y - l.y)
                        + fabsf(a.z - l.z) + fabsf(a.w - l.w);
                    o += fmaxf(fminf(bb.x, h.x) - fmaxf(a.x, l.x), 0.f) * v.x;
                    o += fmaxf(fminf(bb.y, h.y) - fmaxf(a.y, l.y), 0.f) * v.y;
                    o += fmaxf(fminf(bb.z, h.z) - fmaxf(a.z, l.z), 0.f) * v.z;
                    o += fmaxf(fminf(bb.w, h.w) - fmaxf(a.w, l.w), 0.f) * v.w;
                }
                float r = acc[ii] + cd;
                colsum += r;
                ssqf += r * r;
                if (i0 + ii != jglob) ovf += o;
            }
            atomicAdd(&g_colR[jglob], colsum);
            ssq += (double)ssqf;
            ovd += (double)ovf;

            // ------ fused per-node prep (blocks NTRI, NTRI+1 cover all nodes) ------
            if (doPrep) {
                int p = __ldg(par + jglob);
                float leaf = __ldg(leaves + idxj);
                const float HPI = (float)(3.14159265358979323846 * 0.5);
                const float CAP = (float)(3.14159265358979323846 * 0.49999);
                const float4* prl = (const float4*)(resv + (size_t)p * 32);
                const float4* prh = (const float4*)(resv + (size_t)p * 32 + 16);
                float exceed = 0.f, shape = 0.f, pos = 0.f;
#pragma unroll
                for (int u = 0; u < 4; u++) {
                    float4 cl = lj[u], ch = hj[u];
                    float4 rl = prl[u], rh = prh[u];
                    float cc[4] = {cl.x, cl.y, cl.z, cl.w};
                    float ee[4] = {ch.x, ch.y, ch.z, ch.w};
                    float aa[4] = {rl.x, rl.y, rl.z, rl.w};
                    float zz[4] = {rh.x, rh.y, rh.z, rh.w};
#pragma unroll
                    for (int d = 0; d < 4; d++) {
                        float diff = ee[d] - cc[d];
                        exceed += fmaxf((aa[d] + 1.0f) - cc[d], 0.f)
                                + fmaxf(ee[d] - (zz[d] + 1.0f), 0.f);
                        float numer = fmaxf(diff / (zz[d] - aa[d]), EPSF);
                        float sdiv  = fminf(numer / leaf, CAP);
                        shape += fminf(fabsf(tanf((sdiv - 1.0f) * HPI)), CLIPMAXF);
                        pos += fmaxf(expf(-diff), EPSF);
                    }
                }
                eAcc += (double)exceed; shAcc += (double)shape; poAcc += (double)pos;
            }
        }

#pragma unroll
        for (int off = 16; off > 0; off >>= 1) {
            ssq += __shfl_xor_sync(0xffffffffu, ssq, off);
            ovd += __shfl_xor_sync(0xffffffffu, ovd, off);
        }
        if (lane == 0) {
            atomicAdd(&g_sumsqR, ssq);
            atomicAdd(&g_overlap, ovd);
        }
        if (doPrep) {
#pragma unroll
            for (int off = 16; off > 0; off >>= 1) {
                eAcc  += __shfl_xor_sync(0xffffffffu, eAcc,  off);
                shAcc += __shfl_xor_sync(0xffffffffu, shAcc, off);
                poAcc += __shfl_xor_sync(0xffffffffu, poAcc, off);
            }
            if (lane == 0) {
                atomicAdd(&g_exceed,   eAcc);
                atomicAdd(&g_shape,    shAcc);
                atomicAdd(&g_positive, poAcc);
            }
        }
    }

    // ================= last-block finalize + state re-zero =================
    __threadfence();
    if (tid == 0) isLast = (atomicAdd(&g_done, 1u) == NTOT - 1);
    __syncthreads();
    if (!isLast) return;
    __threadfence();

    double s1 = 0.0, s2 = 0.0;
#pragma unroll
    for (int q = 0; q < 4; q++) {
        int j = tid + q * 256;
        double r = (double)__ldcg(&g_colR[j]);
        double a = (double)__ldcg(&g_colA[j]);
        s1 += r * a;
        s2 += r * r;
        g_colR[j] = 0.f;
        g_colA[j] = 0.f;
    }
    __shared__ double r1[8], r2[8];
#pragma unroll
    for (int off = 16; off > 0; off >>= 1) {
        s1 += __shfl_xor_sync(0xffffffffu, s1, off);
        s2 += __shfl_xor_sync(0xffffffffu, s2, off);
    }
    if (lane == 0) { r1[w] = s1; r2[w] = s2; }
    __syncthreads();
    if (tid == 0) {
        double a = 0.0, cc2 = 0.0;
#pragma unroll
        for (int q = 0; q < 8; q++) { a += r1[q]; cc2 += r2[q]; }
        double sumsqR = __ldcg(&g_sumsqR);
        double sumsqA = __ldcg(&g_sumsqA);
        double nR = fmax(sqrt(sumsqR), 1e-15);
        double nA = fmax(sqrt(sumsqA), 1e-15);
        double val = sumsqA / (nA * nA) - 2.0 * (a / nR) / nA + (double)Nn * (cc2 / (nR * nR));
        double lossDist = sqrt(fmax(val, 0.0));
        out[0] = (float)(lossDist + __ldcg(&g_shape) + __ldcg(&g_exceed)
                         + __ldcg(&g_overlap) + __ldcg(&g_positive));
        g_sumsqR = 0.0; g_sumsqA = 0.0; g_overlap = 0.0;
        g_exceed = 0.0; g_shape = 0.0; g_positive = 0.0;
        g_done = 0u;
    }
}

// ---------------- launch ----------------
extern "C" void kernel_launch(void* const* d_in, const int* in_sizes, int n_in,
                              void* d_out, int out_size) {
    const int*   idI    = (const int*)d_in[0];
    const int*   par    = (const int*)d_in[1];
    const float* omega  = (const float*)d_in[2];
    const float* child  = (const float*)d_in[3];
    const float* resv   = (const float*)d_in[4];
    const float* leaves = (const float*)d_in[5];
    const float* layerD = (const float*)d_in[6];
    (void)in_sizes; (void)n_in; (void)out_size;

    k_all<<<NTOT, 256>>>(idI, par, omega, child, resv, leaves, layerD, (float*)d_out);
}